// round 7
// baseline (speedup 1.0000x reference)
#include <cuda_runtime.h>
#include <math.h>

// ---------------------------------------------------------------------------
// SPFBlock fused kernel, sm_103a
// B=4, C_IN=128, H=W=128, L=16384, NUM_HEAD=4, N=32, M_TRI=528, C_POOL=2112,
// DIM=64.  Key identity: attention logits over the 528-dim tri-vectors reduce
// to closed form from the 32-dim t vectors; attn*L is folded into t via sqrt.
// ---------------------------------------------------------------------------

#define BATCH   4
#define CIN     128
#define LTOT    16384           // H*W
#define NHEAD   4
#define NPH     32
#define MTRI    528
#define CPOOL   2112
#define DIMO    64
#define KC      96              // 2112 = 22 * 96

// ------------------------- device scratch (static) -------------------------
__device__ float g_t[BATCH * LTOT * CIN];       // shuffled, LN'd t  (32 MB)
__device__ float g_e[BATCH * LTOT * NHEAD];     // exp(logit)        (1 MB)
__device__ float g_wT[CPOOL * DIMO];            // dr_w transposed [k][o]
__device__ float g_fc1T[DIMO * DIMO];           // fc1_w transposed [c][j]
__device__ float g_umid[BATCH * CIN];           // t at mid, shuffled order
__device__ float g_invnmid[BATCH * NHEAD];      // 1/||y_mid||
__device__ float g_sumexp[BATCH * NHEAD];       // softmax denominators
__device__ unsigned char g_ia[CPOOL];           // tri index i (with head off)
__device__ unsigned char g_ja[CPOOL];           // tri index j (with head off)

// ------------------------------- init kernel -------------------------------
__global__ void k_init(const float* __restrict__ dr_w,
                       const float* __restrict__ fc1_w) {
    int tid = blockIdx.x * blockDim.x + threadIdx.x;
    int nth = gridDim.x * blockDim.x;
    // transpose dr_w [64,2112] -> g_wT [2112,64]
    for (int idx = tid; idx < CPOOL * DIMO; idx += nth) {
        int k = idx >> 6, o = idx & 63;
        g_wT[idx] = dr_w[o * CPOOL + k];
    }
    // transpose fc1_w [64,64] -> g_fc1T [c][j]
    for (int idx = tid; idx < DIMO * DIMO; idx += nth) {
        int c = idx >> 6, j = idx & 63;
        g_fc1T[idx] = fc1_w[j * DIMO + c];
    }
    if (blockIdx.x == 0) {
        for (int m = threadIdx.x; m < MTRI; m += blockDim.x) {
            int i = 0, off = 0;
            while (off + (NPH - i) <= m) { off += NPH - i; i++; }
            int j = i + (m - off);
            #pragma unroll
            for (int h = 0; h < NHEAD; h++) {
                g_ia[h * MTRI + m] = (unsigned char)(h * NPH + i);
                g_ja[h * MTRI + m] = (unsigned char)(h * NPH + j);
            }
        }
        if (threadIdx.x < BATCH * NHEAD) g_sumexp[threadIdx.x] = 0.0f;
    }
}

// ------------------------------- mid kernel --------------------------------
// Compute t at mid position (l = 8192) per batch; store shuffled u and
// 1/||y_mid|| per head.
__global__ void k_mid(const float* __restrict__ x,
                      const float* __restrict__ n1w,
                      const float* __restrict__ n1b) {
    __shared__ float red[CIN];
    __shared__ float us[CIN];
    int b = blockIdx.x, tid = threadIdx.x;
    float v = x[((size_t)b * CIN + tid) * LTOT + (LTOT / 2)];
    red[tid] = v;
    __syncthreads();
    for (int o = 64; o; o >>= 1) { if (tid < o) red[tid] += red[tid + o]; __syncthreads(); }
    float mu = red[0] * (1.0f / 128.0f);
    __syncthreads();
    red[tid] = v * v;
    __syncthreads();
    for (int o = 64; o; o >>= 1) { if (tid < o) red[tid] += red[tid + o]; __syncthreads(); }
    float var = red[0] * (1.0f / 128.0f) - mu * mu;
    float rstd = rsqrtf(var + 1e-5f);
    float xn = (v - mu) * rstd * n1w[tid] + n1b[tid];
    int cp = ((tid & 3) << 5) + (tid >> 2);          // shuffled channel
    us[cp] = xn;
    g_umid[b * CIN + cp] = xn;
    __syncthreads();
    if (tid < NHEAD) {
        float uu = 0.f, s4 = 0.f;
        #pragma unroll
        for (int i = 0; i < NPH; i++) {
            float u = us[tid * NPH + i];
            float u2 = u * u;
            uu += u2; s4 += u2 * u2;
        }
        g_invnmid[b * NHEAD + tid] = rsqrtf(0.5f * (uu * uu + s4));
    }
}

// -------------------------------- LN kernel --------------------------------
// 128 positions per block (128 threads, one position each).
// Dynamic smem: xs[128][129] + su[128] + swv[128] + sbv[128] + sAcc[4]
__global__ void k_ln(const float* __restrict__ x,
                     const float* __restrict__ n1w,
                     const float* __restrict__ n1b) {
    extern __shared__ float sm[];
    float* xs   = sm;                       // 128*129
    float* su   = sm + 128 * 129;           // 128
    float* swv  = su + 128;                 // 128
    float* sbv  = swv + 128;                // 128
    float* sAcc = sbv + 128;                // 4

    int tid = threadIdx.x;
    int blk = blockIdx.x;
    int b   = blk >> 7;                     // 128 blocks per batch image
    int p0  = (blk & 127) << 7;

    su[tid] = g_umid[b * CIN + tid];
    {
        int c = ((tid & 31) << 2) + (tid >> 5);   // inverse shuffle
        swv[tid] = n1w[c];
        sbv[tid] = n1b[c];
    }
    if (tid < NHEAD) sAcc[tid] = 0.0f;

    const float* xb = x + (size_t)b * CIN * LTOT + p0;
    #pragma unroll 4
    for (int cc = 0; cc < CIN; cc++) {
        float v = xb[(size_t)cc * LTOT + tid];
        int cp = ((cc & 3) << 5) + (cc >> 2);
        xs[tid * 129 + cp] = v;
    }
    __syncthreads();

    float* row = xs + tid * 129;
    float s = 0.f, s2 = 0.f;
    #pragma unroll 8
    for (int c = 0; c < CIN; c++) { float v = row[c]; s += v; s2 += v * v; }
    float mu   = s  * (1.0f / 128.0f);
    float var  = s2 * (1.0f / 128.0f) - mu * mu;
    float rstd = rsqrtf(var + 1e-5f);

    int gp = b * LTOT + p0 + tid;
    #pragma unroll
    for (int h = 0; h < NHEAD; h++) {
        float duv = 0.f, dvv = 0.f, suv = 0.f, sv4 = 0.f;
        #pragma unroll 8
        for (int i = 0; i < NPH; i++) {
            int c = h * NPH + i;
            float v = (row[c] - mu) * rstd * swv[c] + sbv[c];
            row[c] = v;
            float u  = su[c];
            float uv = u * v;
            float v2 = v * v;
            duv += uv;
            dvv += v2;
            suv += uv * uv;
            sv4 += v2 * v2;
        }
        float ny2   = 0.5f * (dvv * dvv + sv4);
        float logit = 0.5f * (duv * duv + suv) * rsqrtf(ny2) * g_invnmid[b * NHEAD + h];
        float e = expf(logit);
        g_e[gp * NHEAD + h] = e;
        float we = e;
        #pragma unroll
        for (int o = 16; o; o >>= 1) we += __shfl_xor_sync(0xffffffffu, we, o);
        if ((tid & 31) == 0) atomicAdd(&sAcc[h], we);
    }
    __syncthreads();
    if (tid < NHEAD) atomicAdd(&g_sumexp[b * NHEAD + tid], sAcc[tid]);

    // coalesced store of shuffled/normalized t
    float* tb = g_t + (size_t)(b * LTOT + p0) * CIN;
    #pragma unroll 4
    for (int e2 = 0; e2 < 128; e2++) {
        tb[e2 * CIN + tid] = xs[e2 * 129 + tid];
    }
}

// ------------------------------- main kernel -------------------------------
// 64 positions x 64 outputs per block, 256 threads (4x4 per thread).
// Builds pf chunks on the fly, fused epilogue: +dr_b, LN(64), fc1, GELU.
__global__ __launch_bounds__(256) void k_main(const float* __restrict__ dr_b,
                                              const float* __restrict__ n2w,
                                              const float* __restrict__ n2b,
                                              const float* __restrict__ fc1_b,
                                              float* __restrict__ out) {
    extern __shared__ float sm[];
    float* sT  = sm;                        // 64*129 = 8256 floats
    float* sPF = sm + 8256;                 // 96*64  = 6144
    float* sW  = sPF + 6144;                // 96*68  = 6528
    float* sS  = sW + 6528;                 // 256
    float* sF  = sS + 256;                  // 64*68  = 4352
    unsigned char* sIa = (unsigned char*)(sF + 4352);   // 2112
    unsigned char* sJa = sIa + CPOOL;                    // 2112

    int tid = threadIdx.x;
    int gp0 = blockIdx.x << 6;              // global position base
    int b   = gp0 >> 14;
    int p0  = gp0 & (LTOT - 1);
    int tx  = tid & 15, ty = tid >> 4;
    int tx4 = tx << 2,  ty4 = ty << 2;

    // per-(pos,head) scale sqrt(L * attn)
    {
        int pos = tid >> 2, h = tid & 3;
        float e  = g_e[(gp0 + pos) * NHEAD + h];
        float se = g_sumexp[b * NHEAD + h];
        sS[tid] = sqrtf(16384.0f * e / se);
    }
    for (int idx = tid; idx < CPOOL; idx += 256) { sIa[idx] = g_ia[idx]; sJa[idx] = g_ja[idx]; }
    #pragma unroll
    for (int e2 = 0; e2 < 16; e2++) {
        int idx = tid + (e2 << 8);
        sF[(idx >> 6) * 68 + (idx & 63)] = g_fc1T[idx];
    }
    __syncthreads();

    // scaled t tile
    const float* tsrc = g_t + (size_t)gp0 * CIN;
    #pragma unroll
    for (int e2 = 0; e2 < 32; e2++) {
        int idx = tid + (e2 << 8);
        int pos = idx >> 7, c = idx & 127;
        sT[pos * 129 + c] = tsrc[idx] * sS[(pos << 2) + (c >> 5)];
    }

    float acc[4][4] = {};
    for (int kb = 0; kb < CPOOL; kb += KC) {
        __syncthreads();
        const float* wsrc = g_wT + kb * DIMO;
        #pragma unroll
        for (int e2 = 0; e2 < 24; e2++) {                // 96*64 = 6144
            int idx = tid + (e2 << 8);
            sW[(idx >> 6) * 68 + (idx & 63)] = wsrc[idx];
        }
        #pragma unroll
        for (int e2 = 0; e2 < 24; e2++) {
            int idx = tid + (e2 << 8);
            int k = idx >> 6, pos = idx & 63;
            int kg = kb + k;
            sPF[(k << 6) + pos] = sT[pos * 129 + sIa[kg]] * sT[pos * 129 + sJa[kg]];
        }
        __syncthreads();
        #pragma unroll 4
        for (int k = 0; k < KC; k++) {
            float4 p = *reinterpret_cast<const float4*>(sPF + (k << 6) + ty4);
            float4 w = *reinterpret_cast<const float4*>(sW + k * 68 + tx4);
            acc[0][0] += p.x * w.x; acc[0][1] += p.x * w.y; acc[0][2] += p.x * w.z; acc[0][3] += p.x * w.w;
            acc[1][0] += p.y * w.x; acc[1][1] += p.y * w.y; acc[1][2] += p.y * w.z; acc[1][3] += p.y * w.w;
            acc[2][0] += p.z * w.x; acc[2][1] += p.z * w.y; acc[2][2] += p.z * w.z; acc[2][3] += p.z * w.w;
            acc[3][0] += p.w * w.x; acc[3][1] += p.w * w.y; acc[3][2] += p.w * w.z; acc[3][3] += p.w * w.w;
        }
    }
    __syncthreads();

    // ---- epilogue: +dr_b, LayerNorm(64), fc1(64x64), GELU(exact), store ----
    float* zt = sPF;                        // [pos][68]
    #pragma unroll
    for (int r = 0; r < 4; r++)
        #pragma unroll
        for (int c = 0; c < 4; c++)
            zt[(ty4 + r) * 68 + tx4 + c] = acc[r][c] + dr_b[tx4 + c];
    __syncthreads();

    {
        int pos = tid >> 2, q = tid & 3;
        float* zr = zt + pos * 68 + (q << 4);
        float s = 0.f, s2 = 0.f;
        #pragma unroll
        for (int c = 0; c < 16; c++) { float v = zr[c]; s += v; s2 += v * v; }
        s  += __shfl_xor_sync(0xffffffffu, s, 1);
        s2 += __shfl_xor_sync(0xffffffffu, s2, 1);
        s  += __shfl_xor_sync(0xffffffffu, s, 2);
        s2 += __shfl_xor_sync(0xffffffffu, s2, 2);
        float mu   = s  * (1.0f / 64.0f);
        float var  = s2 * (1.0f / 64.0f) - mu * mu;
        float rstd = rsqrtf(var + 1e-5f);
        #pragma unroll
        for (int c = 0; c < 16; c++) {
            int cc = (q << 4) + c;
            zr[c] = (zr[c] - mu) * rstd * n2w[cc] + n2b[cc];
        }
    }
    __syncthreads();

    float a2[4][4] = {};
    #pragma unroll 8
    for (int c = 0; c < DIMO; c++) {
        float4 f = *reinterpret_cast<const float4*>(sF + c * 68 + tx4);
        float z0 = zt[(ty4 + 0) * 68 + c];
        float z1 = zt[(ty4 + 1) * 68 + c];
        float z2 = zt[(ty4 + 2) * 68 + c];
        float z3 = zt[(ty4 + 3) * 68 + c];
        a2[0][0] += z0 * f.x; a2[0][1] += z0 * f.y; a2[0][2] += z0 * f.z; a2[0][3] += z0 * f.w;
        a2[1][0] += z1 * f.x; a2[1][1] += z1 * f.y; a2[1][2] += z1 * f.z; a2[1][3] += z1 * f.w;
        a2[2][0] += z2 * f.x; a2[2][1] += z2 * f.y; a2[2][2] += z2 * f.z; a2[2][3] += z2 * f.w;
        a2[3][0] += z3 * f.x; a2[3][1] += z3 * f.y; a2[3][2] += z3 * f.z; a2[3][3] += z3 * f.w;
    }
    float* zo = sW;                         // [o][68]
    #pragma unroll
    for (int r = 0; r < 4; r++)
        #pragma unroll
        for (int j = 0; j < 4; j++) {
            float v = a2[r][j] + fc1_b[tx4 + j];
            v = 0.5f * v * (1.0f + erff(v * 0.70710678118654752f));
            zo[(tx4 + j) * 68 + ty4 + r] = v;
        }
    __syncthreads();

    float* ob = out + (size_t)b * DIMO * LTOT + p0;
    #pragma unroll
    for (int e2 = 0; e2 < 16; e2++) {
        int idx = tid + (e2 << 8);
        int o = idx >> 6, pos = idx & 63;
        ob[(size_t)o * LTOT + pos] = zo[o * 68 + pos];
    }
}

// ------------------------------- launch -----------------------------------
extern "C" void kernel_launch(void* const* d_in, const int* in_sizes, int n_in,
                              void* d_out, int out_size) {
    const float* x    = (const float*)d_in[0];
    const float* n1w  = (const float*)d_in[1];
    const float* n1b  = (const float*)d_in[2];
    const float* drw  = (const float*)d_in[3];
    const float* drb  = (const float*)d_in[4];
    const float* n2w  = (const float*)d_in[5];
    const float* n2b  = (const float*)d_in[6];
    const float* f1w  = (const float*)d_in[7];
    const float* f1b  = (const float*)d_in[8];
    float* out = (float*)d_out;

    const int SMEM_LN   = (128 * 129 + 3 * 128 + 4) * 4;   // 67600
    const int SMEM_MAIN = (8256 + 6144 + 6528 + 256 + 4352) * 4 + 2 * CPOOL; // 106368

    cudaFuncSetAttribute(k_ln,   cudaFuncAttributeMaxDynamicSharedMemorySize, SMEM_LN);
    cudaFuncSetAttribute(k_main, cudaFuncAttributeMaxDynamicSharedMemorySize, SMEM_MAIN);

    k_init<<<64, 256>>>(drw, f1w);
    k_mid<<<BATCH, 128>>>(x, n1w, n1b);
    k_ln<<<(BATCH * LTOT) / 128, 128, SMEM_LN>>>(x, n1w, n1b);
    k_main<<<(BATCH * LTOT) / 64, 256, SMEM_MAIN>>>(drb, n2w, n2b, f1b, out);
}